// round 1
// baseline (speedup 1.0000x reference)
#include <cuda_runtime.h>

#define B_ 8
#define C_ 256
#define L_ 4096
#define NH_ 4
#define D_ 64
#define NB_ 64   // number of query/key blocks (L/64)
#define T_ 6     // top-k blocks
#define BH_ 32   // B*NH

// ---------------- scratch (device globals; no allocs) ----------------
__device__ float g_q [BH_*L_*D_];
__device__ float g_k [BH_*L_*D_];
__device__ float g_v [BH_*L_*D_];
__device__ float g_cq[BH_*L_*D_];
__device__ float g_ck[BH_*L_*D_];
__device__ float g_qb[BH_*NB_*D_];
__device__ float g_kb[BH_*NB_*D_];
__device__ int   g_lut[BH_*NB_*T_];
__device__ float g_kvb[(size_t)BH_*NB_*D_*D_];
__device__ float g_ksum[BH_*NB_*D_];
__device__ float g_kvt[BH_*D_*D_];
__device__ float g_kst[BH_*D_];
__device__ float g_obuf[BH_*L_*D_];

// ---------------- K1: qkv = W(768x256) @ X(256,4096), write q/k/v as (B,NH,L,D) ----------------
__global__ void k_qkv(const float* __restrict__ x, const float* __restrict__ w) {
    __shared__ float Xs[16][64];
    __shared__ float Ws[16][65];
    const int b  = blockIdx.z;
    const int l0 = blockIdx.x * 64;
    const int o0 = blockIdx.y * 64;
    const int tid = threadIdx.x;
    const int ty = tid >> 4, tx = tid & 15;
    float acc[4][4] = {};
    const float* xb = x + (size_t)b * C_ * L_;
    for (int c0 = 0; c0 < C_; c0 += 16) {
        {   // X tile [c][l], 16x64
            int i = tid * 4, c = i >> 6, l = i & 63;
            float4 v = *reinterpret_cast<const float4*>(&xb[(size_t)(c0 + c) * L_ + l0 + l]);
            *reinterpret_cast<float4*>(&Xs[c][l]) = v;
        }
        {   // W tile, stored transposed as Ws[c][o]
            int i = tid * 4, o = i >> 4, c = i & 15;
            float4 v = *reinterpret_cast<const float4*>(&w[(size_t)(o0 + o) * C_ + c0 + c]);
            Ws[c + 0][o] = v.x; Ws[c + 1][o] = v.y; Ws[c + 2][o] = v.z; Ws[c + 3][o] = v.w;
        }
        __syncthreads();
#pragma unroll
        for (int c = 0; c < 16; c++) {
            float a[4], bb[4];
#pragma unroll
            for (int i = 0; i < 4; i++) a[i] = Xs[c][ty * 4 + i];
#pragma unroll
            for (int j = 0; j < 4; j++) bb[j] = Ws[c][tx * 4 + j];
#pragma unroll
            for (int i = 0; i < 4; i++)
#pragma unroll
                for (int j = 0; j < 4; j++) acc[i][j] += a[i] * bb[j];
        }
        __syncthreads();
    }
    // o0 is 64-aligned: whole tile is one (part, head)
    const int part = o0 >> 8, h = (o0 >> 6) & 3;
    float* dst = (part == 0) ? g_q : (part == 1) ? g_k : g_v;
    dst += (size_t)(b * NH_ + h) * L_ * D_;
#pragma unroll
    for (int i = 0; i < 4; i++) {
        int l = l0 + ty * 4 + i;
        *reinterpret_cast<float4*>(&dst[(size_t)l * D_ + tx * 4]) =
            make_float4(acc[i][0], acc[i][1], acc[i][2], acc[i][3]);
    }
}

// ---------------- K2: per-block token means qb/kb ----------------
__global__ void k_blockmean() {
    const int n = blockIdx.x, bh = blockIdx.y, which = blockIdx.z;
    const float* src = which ? g_k : g_q;
    float* dst = which ? g_kb : g_qb;
    const int d = threadIdx.x;
    const float* p = src + ((size_t)bh * L_ + n * 64) * D_;
    float s = 0.f;
#pragma unroll 8
    for (int i = 0; i < 64; i++) s += p[i * D_ + d];
    dst[((size_t)bh * NB_ + n) * D_ + d] = s * (1.f / 64.f);
}

// ---------------- K3: block scores + top-6 (ties -> lowest index, matches lax.top_k) ----------------
__global__ void k_topk() {
    __shared__ float QB[64][64];
    __shared__ float KB[64][64];
    __shared__ float S[64][64];
    const int bh = blockIdx.x;
    for (int i = threadIdx.x; i < 4096; i += 256) {
        QB[i >> 6][i & 63] = g_qb[(size_t)bh * 4096 + i];
        KB[i >> 6][i & 63] = g_kb[(size_t)bh * 4096 + i];
    }
    __syncthreads();
    const int r = threadIdx.x >> 2, cb = (threadIdx.x & 3) * 16;
    for (int c = cb; c < cb + 16; c++) {
        float s = 0.f;
#pragma unroll 8
        for (int d = 0; d < 64; d++) s += QB[r][d] * KB[c][d];
        S[r][c] = s;
    }
    __syncthreads();
    if (threadIdx.x < 64) {
        const int rr = threadIdx.x;
        unsigned long long used = 0ull;
        for (int t = 0; t < T_; t++) {
            float best = -3.4e38f; int bi = 0;
            for (int c = 0; c < 64; c++) {
                if ((used >> c) & 1ull) continue;
                float v = S[rr][c];
                if (v > best) { best = v; bi = c; }
            }
            used |= 1ull << bi;
            g_lut[((size_t)bh * NB_ + rr) * T_ + t] = bi;
        }
    }
}

// ---------------- K4: sparse attention over gathered top-k blocks ----------------
__global__ void k_sattn() {
    extern __shared__ float sm[];
    float* Qs = sm;             // 64*68
    float* Ks = sm + 64 * 68;   // 64*68 (reused for V)
    float* Ss = sm + 2 * 64 * 68; // 64*388
    __shared__ int luts[T_];
    const int n = blockIdx.x, bh = blockIdx.y;
    const int tid = threadIdx.x;
    const float* qp = g_q + ((size_t)bh * L_ + n * 64) * D_;
    for (int i = tid * 4; i < 4096; i += 1024) {
        int r = i >> 6, d = i & 63;
        *reinterpret_cast<float4*>(&Qs[r * 68 + d]) = *reinterpret_cast<const float4*>(&qp[i]);
    }
    if (tid < T_) luts[tid] = g_lut[((size_t)bh * NB_ + n) * T_ + tid];
    __syncthreads();
    const int ty = tid >> 4, tx = tid & 15, r0 = ty * 4, c0 = tx * 4;

    // scores S = scale * Q @ K_t^T for 6 gathered key blocks
    for (int t = 0; t < T_; t++) {
        __syncthreads();
        const float* kp = g_k + ((size_t)bh * L_ + luts[t] * 64) * D_;
        for (int i = tid * 4; i < 4096; i += 1024) {
            int r = i >> 6, d = i & 63;
            *reinterpret_cast<float4*>(&Ks[r * 68 + d]) = *reinterpret_cast<const float4*>(&kp[i]);
        }
        __syncthreads();
        float acc[4][4] = {};
        for (int d = 0; d < 64; d += 4) {
            float4 a[4], bv[4];
#pragma unroll
            for (int i = 0; i < 4; i++) a[i] = *reinterpret_cast<float4*>(&Qs[(r0 + i) * 68 + d]);
#pragma unroll
            for (int j = 0; j < 4; j++) bv[j] = *reinterpret_cast<float4*>(&Ks[(c0 + j) * 68 + d]);
#pragma unroll
            for (int i = 0; i < 4; i++)
#pragma unroll
                for (int j = 0; j < 4; j++)
                    acc[i][j] += a[i].x * bv[j].x + a[i].y * bv[j].y + a[i].z * bv[j].z + a[i].w * bv[j].w;
        }
#pragma unroll
        for (int i = 0; i < 4; i++)
#pragma unroll
            for (int j = 0; j < 4; j++)
                Ss[(r0 + i) * 388 + t * 64 + c0 + j] = acc[i][j] * 0.125f;
    }
    __syncthreads();
    {   // row softmax over 384 cols: 4 lanes per row
        const int r = tid >> 2, ln = tid & 3;
        float m = -3.4e38f;
        for (int c = ln; c < 384; c += 4) m = fmaxf(m, Ss[r * 388 + c]);
        m = fmaxf(m, __shfl_xor_sync(0xffffffffu, m, 1));
        m = fmaxf(m, __shfl_xor_sync(0xffffffffu, m, 2));
        float s = 0.f;
        for (int c = ln; c < 384; c += 4) { float e = __expf(Ss[r * 388 + c] - m); Ss[r * 388 + c] = e; s += e; }
        s += __shfl_xor_sync(0xffffffffu, s, 1);
        s += __shfl_xor_sync(0xffffffffu, s, 2);
        float inv = 1.f / s;
        for (int c = ln; c < 384; c += 4) Ss[r * 388 + c] *= inv;
    }
    // o_s = P @ V_gathered
    float oacc[4][4] = {};
    for (int t = 0; t < T_; t++) {
        __syncthreads();
        const float* vp = g_v + ((size_t)bh * L_ + luts[t] * 64) * D_;
        for (int i = tid * 4; i < 4096; i += 1024) {
            int r = i >> 6, d = i & 63;
            *reinterpret_cast<float4*>(&Ks[r * 68 + d]) = *reinterpret_cast<const float4*>(&vp[i]);
        }
        __syncthreads();
        for (int kk = 0; kk < 64; kk++) {
            float a[4];
#pragma unroll
            for (int i = 0; i < 4; i++) a[i] = Ss[(r0 + i) * 388 + t * 64 + kk];
            float4 bv = *reinterpret_cast<float4*>(&Ks[kk * 68 + c0]);
#pragma unroll
            for (int i = 0; i < 4; i++) {
                oacc[i][0] += a[i] * bv.x; oacc[i][1] += a[i] * bv.y;
                oacc[i][2] += a[i] * bv.z; oacc[i][3] += a[i] * bv.w;
            }
        }
    }
    float* op = g_obuf + ((size_t)bh * L_ + n * 64) * D_;
#pragma unroll
    for (int i = 0; i < 4; i++)
        *reinterpret_cast<float4*>(&op[(r0 + i) * 64 + c0]) =
            make_float4(oacc[i][0], oacc[i][1], oacc[i][2], oacc[i][3]);
}

// ---------------- K5a: feature map = softmax over D for q and k ----------------
__global__ void k_featmap() {
    const int which = blockIdx.y;
    const float* src = which ? g_k : g_q;
    float* dst = which ? g_ck : g_cq;
    const int warp = threadIdx.x >> 5, lane = threadIdx.x & 31;
    const size_t row = (size_t)blockIdx.x * 8 + warp;
    const float* p = src + row * 64;
    float v0 = p[lane], v1 = p[lane + 32];
    float m = fmaxf(v0, v1);
#pragma unroll
    for (int o = 16; o; o >>= 1) m = fmaxf(m, __shfl_xor_sync(0xffffffffu, m, o));
    v0 = __expf(v0 - m); v1 = __expf(v1 - m);
    float s = v0 + v1;
#pragma unroll
    for (int o = 16; o; o >>= 1) s += __shfl_xor_sync(0xffffffffu, s, o);
    float inv = 1.f / s;
    dst[row * 64 + lane] = v0 * inv;
    dst[row * 64 + lane + 32] = v1 * inv;
}

// ---------------- K5b: per key block: kvb = cK^T @ V (DxD), ksum = colsum(cK) ----------------
__global__ void k_kvb() {
    __shared__ float CK[64][68];
    __shared__ float Vs[64][68];
    const int m = blockIdx.x, bh = blockIdx.y;
    const int tid = threadIdx.x;
    const float* ckp = g_ck + ((size_t)bh * L_ + m * 64) * D_;
    const float* vp  = g_v  + ((size_t)bh * L_ + m * 64) * D_;
    for (int i = tid * 4; i < 4096; i += 1024) {
        int r = i >> 6, d = i & 63;
        *reinterpret_cast<float4*>(&CK[r][d]) = *reinterpret_cast<const float4*>(&ckp[i]);
        *reinterpret_cast<float4*>(&Vs[r][d]) = *reinterpret_cast<const float4*>(&vp[i]);
    }
    __syncthreads();
    const int ty = tid >> 4, tx = tid & 15, d0 = ty * 4, e0 = tx * 4;
    float acc[4][4] = {};
    for (int k = 0; k < 64; k++) {
        float a[4];
#pragma unroll
        for (int i = 0; i < 4; i++) a[i] = CK[k][d0 + i];
        float4 bv = *reinterpret_cast<float4*>(&Vs[k][e0]);
#pragma unroll
        for (int i = 0; i < 4; i++) {
            acc[i][0] += a[i] * bv.x; acc[i][1] += a[i] * bv.y;
            acc[i][2] += a[i] * bv.z; acc[i][3] += a[i] * bv.w;
        }
    }
    float* dst = g_kvb + (size_t)(bh * NB_ + m) * D_ * D_;
#pragma unroll
    for (int i = 0; i < 4; i++)
        *reinterpret_cast<float4*>(&dst[(d0 + i) * 64 + e0]) =
            make_float4(acc[i][0], acc[i][1], acc[i][2], acc[i][3]);
    if (tid < 64) {
        float s = 0.f;
#pragma unroll 8
        for (int k = 0; k < 64; k++) s += CK[k][tid];
        g_ksum[(size_t)(bh * NB_ + m) * D_ + tid] = s;
    }
}

// ---------------- K5c: totals over all key blocks ----------------
__global__ void k_totals() {
    const int bh = blockIdx.x, tid = threadIdx.x;
    for (int i = tid; i < 4096; i += 256) {
        const float* p = g_kvb + (size_t)bh * NB_ * 4096 + i;
        float s = 0.f;
#pragma unroll 8
        for (int m = 0; m < 64; m++) s += p[(size_t)m * 4096];
        g_kvt[(size_t)bh * 4096 + i] = s;
    }
    if (tid < 64) {
        const float* p = g_ksum + (size_t)bh * NB_ * 64 + tid;
        float s = 0.f;
#pragma unroll 8
        for (int m = 0; m < 64; m++) s += p[m * 64];
        g_kst[bh * 64 + tid] = s;
    }
}

// ---------------- K5d: linear path per query block + proj_l, add into obuf ----------------
__global__ void k_linfinal(const float* __restrict__ plw, const float* __restrict__ plb) {
    __shared__ float A[64][68];   // KVQ (d,e) then OL (r,d)
    __shared__ float Bm[64][68];  // CQ (r,d) then PW (e,d)
    __shared__ float ksq[64], den_s[64];
    __shared__ int luts[T_];
    const int n = blockIdx.x, bh = blockIdx.y;
    const int tid = threadIdx.x;
    if (tid < T_) luts[tid] = g_lut[((size_t)bh * NB_ + n) * T_ + tid];
    __syncthreads();
    // kv_q = kv_total - sum of selected kvb (complement trick)
    for (int i = tid; i < 4096; i += 256) {
        float s = g_kvt[(size_t)bh * 4096 + i];
#pragma unroll
        for (int t = 0; t < T_; t++) s -= g_kvb[(size_t)(bh * NB_ + luts[t]) * 4096 + i];
        A[i >> 6][i & 63] = s;
    }
    if (tid < 64) {
        float s = g_kst[bh * 64 + tid];
#pragma unroll
        for (int t = 0; t < T_; t++) s -= g_ksum[(size_t)(bh * NB_ + luts[t]) * 64 + tid];
        ksq[tid] = s;
    }
    const float* cqp = g_cq + ((size_t)bh * L_ + n * 64) * D_;
    for (int i = tid * 4; i < 4096; i += 1024) {
        int r = i >> 6, d = i & 63;
        *reinterpret_cast<float4*>(&Bm[r][d]) = *reinterpret_cast<const float4*>(&cqp[i]);
    }
    __syncthreads();
    const int ty = tid >> 4, tx = tid & 15, r0 = ty * 4, c0 = tx * 4;
    float acc[4][4] = {};
    for (int d = 0; d < 64; d++) {
        float a[4];
#pragma unroll
        for (int i = 0; i < 4; i++) a[i] = Bm[r0 + i][d];
        float4 bv = *reinterpret_cast<float4*>(&A[d][c0]);
#pragma unroll
        for (int i = 0; i < 4; i++) {
            acc[i][0] += a[i] * bv.x; acc[i][1] += a[i] * bv.y;
            acc[i][2] += a[i] * bv.z; acc[i][3] += a[i] * bv.w;
        }
    }
    if (tid < 64) {
        float s = 0.f;
#pragma unroll 8
        for (int d = 0; d < 64; d++) s += Bm[tid][d] * ksq[d];
        den_s[tid] = s;
    }
    __syncthreads();
    // o_l -> A (overwrite KVQ)
#pragma unroll
    for (int i = 0; i < 4; i++) {
        float inv = 1.f / (den_s[r0 + i] + 1e-6f);
#pragma unroll
        for (int j = 0; j < 4; j++) A[r0 + i][c0 + j] = acc[i][j] * inv;
    }
    // PW -> Bm (overwrite CQ)
    for (int i = tid * 4; i < 4096; i += 1024) {
        int e = i >> 6, d = i & 63;
        *reinterpret_cast<float4*>(&Bm[e][d]) = *reinterpret_cast<const float4*>(&plw[i]);
    }
    __syncthreads();
    float acc2[4][4] = {};
    for (int d = 0; d < 64; d++) {
        float a[4], bb[4];
#pragma unroll
        for (int i = 0; i < 4; i++) a[i] = A[r0 + i][d];
#pragma unroll
        for (int j = 0; j < 4; j++) bb[j] = Bm[c0 + j][d];
#pragma unroll
        for (int i = 0; i < 4; i++)
#pragma unroll
            for (int j = 0; j < 4; j++) acc2[i][j] += a[i] * bb[j];
    }
    float pb0 = plb[c0], pb1 = plb[c0 + 1], pb2 = plb[c0 + 2], pb3 = plb[c0 + 3];
    float* op = g_obuf + ((size_t)bh * L_ + n * 64) * D_;
#pragma unroll
    for (int i = 0; i < 4; i++) {
        float4 v = *reinterpret_cast<float4*>(&op[(r0 + i) * 64 + c0]);
        v.x += acc2[i][0] + pb0; v.y += acc2[i][1] + pb1;
        v.z += acc2[i][2] + pb2; v.w += acc2[i][3] + pb3;
        *reinterpret_cast<float4*>(&op[(r0 + i) * 64 + c0]) = v;
    }
}

// ---------------- K6: out_proj GEMM, (256x256) @ (256,4096) per batch ----------------
__global__ void k_outproj(const float* __restrict__ w2, float* __restrict__ out) {
    __shared__ float As[16][68]; // [c][l]
    __shared__ float Ws[16][65]; // [c][co]
    const int l0 = blockIdx.x * 64, co0 = blockIdx.y * 64, b = blockIdx.z;
    const int tid = threadIdx.x;
    const int ty = tid >> 4, tx = tid & 15;
    float acc[4][4] = {};
    for (int c0 = 0; c0 < C_; c0 += 16) {
        const int h = c0 >> 6, d0 = c0 & 63;
        const float* ap = g_obuf + ((size_t)(b * NH_ + h) * L_ + l0) * D_ + d0;
        {   // load [l][d] 64x16, store transposed As[d][l]
            int i = tid * 4, l = i >> 4, d = i & 15;
            float4 v = *reinterpret_cast<const float4*>(&ap[(size_t)l * D_ + d]);
            As[d + 0][l] = v.x; As[d + 1][l] = v.y; As[d + 2][l] = v.z; As[d + 3][l] = v.w;
        }
        {
            int i = tid * 4, o = i >> 4, c = i & 15;
            float4 v = *reinterpret_cast<const float4*>(&w2[(size_t)(co0 + o) * C_ + c0 + c]);
            Ws[c + 0][o] = v.x; Ws[c + 1][o] = v.y; Ws[c + 2][o] = v.z; Ws[c + 3][o] = v.w;
        }
        __syncthreads();
#pragma unroll
        for (int c = 0; c < 16; c++) {
            float a[4], bb[4];
#pragma unroll
            for (int i = 0; i < 4; i++) a[i] = Ws[c][ty * 4 + i];   // co
#pragma unroll
            for (int j = 0; j < 4; j++) bb[j] = As[c][tx * 4 + j];  // l
#pragma unroll
            for (int i = 0; i < 4; i++)
#pragma unroll
                for (int j = 0; j < 4; j++) acc[i][j] += a[i] * bb[j];
        }
        __syncthreads();
    }
#pragma unroll
    for (int i = 0; i < 4; i++) {
        int co = co0 + ty * 4 + i;
        *reinterpret_cast<float4*>(&out[(size_t)b * C_ * L_ + (size_t)co * L_ + l0 + tx * 4]) =
            make_float4(acc[i][0], acc[i][1], acc[i][2], acc[i][3]);
    }
}

// ---------------- launch ----------------
extern "C" void kernel_launch(void* const* d_in, const int* in_sizes, int n_in,
                              void* d_out, int out_size) {
    const float* x     = (const float*)d_in[0];
    const float* qkv_w = (const float*)d_in[1];
    const float* out_w = (const float*)d_in[2];
    const float* plw   = (const float*)d_in[3];
    const float* plb   = (const float*)d_in[4];
    float* out = (float*)d_out;

    const int sattn_smem = (2 * 64 * 68 + 64 * 388) * (int)sizeof(float); // 134144 B
    cudaFuncSetAttribute(k_sattn, cudaFuncAttributeMaxDynamicSharedMemorySize, sattn_smem);

    k_qkv      <<<dim3(L_ / 64, 12, B_), 256>>>(x, qkv_w);
    k_blockmean<<<dim3(NB_, BH_, 2), 64>>>();
    k_topk     <<<BH_, 256>>>();
    k_sattn    <<<dim3(NB_, BH_), 256, sattn_smem>>>();
    k_featmap  <<<dim3(BH_ * L_ / 8, 2), 256>>>();
    k_kvb      <<<dim3(NB_, BH_), 256>>>();
    k_totals   <<<BH_, 256>>>();
    k_linfinal <<<dim3(NB_, BH_), 256>>>(plw, plb);
    k_outproj  <<<dim3(L_ / 64, C_ / 64, B_), 256>>>(out_w, out);
}

// round 2
// speedup vs baseline: 1.1336x; 1.1336x over previous
#include <cuda_runtime.h>

#define B_ 8
#define C_ 256
#define L_ 4096
#define NH_ 4
#define D_ 64
#define NB_ 64   // number of query/key blocks (L/64)
#define T_ 6     // top-k blocks
#define BH_ 32   // B*NH

// ---------------- scratch (device globals; no allocs) ----------------
__device__ float g_q [BH_*L_*D_];
__device__ float g_k [BH_*L_*D_];
__device__ float g_v [BH_*L_*D_];
__device__ float g_cq[BH_*L_*D_];
__device__ float g_ck[BH_*L_*D_];
__device__ float g_qb[BH_*NB_*D_];
__device__ float g_kb[BH_*NB_*D_];
__device__ int   g_lut[BH_*NB_*T_];
__device__ float g_kvb[(size_t)BH_*NB_*D_*D_];
__device__ float g_ksum[BH_*NB_*D_];
__device__ float g_kvt[BH_*D_*D_];
__device__ float g_kst[BH_*D_];
__device__ float g_obuf[BH_*L_*D_];

// ---------------- K1: qkv = W(768x256) @ X(256,4096), write q/k/v as (B,NH,L,D) ----------------
__global__ void k_qkv(const float* __restrict__ x, const float* __restrict__ w) {
    __shared__ float Xs[16][64];
    __shared__ float Ws[16][65];
    const int b  = blockIdx.z;
    const int l0 = blockIdx.x * 64;
    const int o0 = blockIdx.y * 64;
    const int tid = threadIdx.x;
    const int ty = tid >> 4, tx = tid & 15;
    float acc[4][4] = {};
    const float* xb = x + (size_t)b * C_ * L_;
    for (int c0 = 0; c0 < C_; c0 += 16) {
        {   // X tile [c][l], 16x64
            int i = tid * 4, c = i >> 6, l = i & 63;
            float4 v = *reinterpret_cast<const float4*>(&xb[(size_t)(c0 + c) * L_ + l0 + l]);
            *reinterpret_cast<float4*>(&Xs[c][l]) = v;
        }
        {   // W tile, stored transposed as Ws[c][o]
            int i = tid * 4, o = i >> 4, c = i & 15;
            float4 v = *reinterpret_cast<const float4*>(&w[(size_t)(o0 + o) * C_ + c0 + c]);
            Ws[c + 0][o] = v.x; Ws[c + 1][o] = v.y; Ws[c + 2][o] = v.z; Ws[c + 3][o] = v.w;
        }
        __syncthreads();
#pragma unroll
        for (int c = 0; c < 16; c++) {
            float a[4], bb[4];
#pragma unroll
            for (int i = 0; i < 4; i++) a[i] = Xs[c][ty * 4 + i];
#pragma unroll
            for (int j = 0; j < 4; j++) bb[j] = Ws[c][tx * 4 + j];
#pragma unroll
            for (int i = 0; i < 4; i++)
#pragma unroll
                for (int j = 0; j < 4; j++) acc[i][j] += a[i] * bb[j];
        }
        __syncthreads();
    }
    // o0 is 64-aligned: whole tile is one (part, head)
    const int part = o0 >> 8, h = (o0 >> 6) & 3;
    float* dst = (part == 0) ? g_q : (part == 1) ? g_k : g_v;
    dst += (size_t)(b * NH_ + h) * L_ * D_;
#pragma unroll
    for (int i = 0; i < 4; i++) {
        int l = l0 + ty * 4 + i;
        *reinterpret_cast<float4*>(&dst[(size_t)l * D_ + tx * 4]) =
            make_float4(acc[i][0], acc[i][1], acc[i][2], acc[i][3]);
    }
}

// ---------------- K2: per-block token means qb/kb ----------------
__global__ void k_blockmean() {
    const int n = blockIdx.x, bh = blockIdx.y, which = blockIdx.z;
    const float* src = which ? g_k : g_q;
    float* dst = which ? g_kb : g_qb;
    const int d = threadIdx.x;
    const float* p = src + ((size_t)bh * L_ + n * 64) * D_;
    float s = 0.f;
#pragma unroll 8
    for (int i = 0; i < 64; i++) s += p[i * D_ + d];
    dst[((size_t)bh * NB_ + n) * D_ + d] = s * (1.f / 64.f);
}

// ---------------- K3: block scores + top-6 (ties -> lowest index, matches lax.top_k) ----------------
__global__ void k_topk() {
    __shared__ float QB[64][64];
    __shared__ float KB[64][64];
    __shared__ float S[64][64];
    const int bh = blockIdx.x;
    for (int i = threadIdx.x; i < 4096; i += 256) {
        QB[i >> 6][i & 63] = g_qb[(size_t)bh * 4096 + i];
        KB[i >> 6][i & 63] = g_kb[(size_t)bh * 4096 + i];
    }
    __syncthreads();
    const int r = threadIdx.x >> 2, cb = (threadIdx.x & 3) * 16;
    for (int c = cb; c < cb + 16; c++) {
        float s = 0.f;
#pragma unroll 8
        for (int d = 0; d < 64; d++) s += QB[r][d] * KB[c][d];
        S[r][c] = s;
    }
    __syncthreads();
    if (threadIdx.x < 64) {
        const int rr = threadIdx.x;
        unsigned long long used = 0ull;
        for (int t = 0; t < T_; t++) {
            float best = -3.4e38f; int bi = 0;
            for (int c = 0; c < 64; c++) {
                if ((used >> c) & 1ull) continue;
                float v = S[rr][c];
                if (v > best) { best = v; bi = c; }
            }
            used |= 1ull << bi;
            g_lut[((size_t)bh * NB_ + rr) * T_ + t] = bi;
        }
    }
}

// ---------------- K4: sparse attention, flash-style online softmax ----------------
// smem: Qs[64][68] | Ks[64][68] (K tile, then reused for P tile) | Vs[64][68]
__global__ void __launch_bounds__(256, 4) k_sattn() {
    extern __shared__ float sm[];
    float* Qs = sm;               // 64*68
    float* Ks = sm + 64 * 68;     // 64*68  (K, then P)
    float* Vs = sm + 2 * 64 * 68; // 64*68
    __shared__ int luts[T_];
    const int n = blockIdx.x, bh = blockIdx.y;
    const int tid = threadIdx.x;
    const float* qp = g_q + ((size_t)bh * L_ + n * 64) * D_;
#pragma unroll
    for (int i = tid * 4; i < 4096; i += 1024) {
        int r = i >> 6, d = i & 63;
        *reinterpret_cast<float4*>(&Qs[r * 68 + d]) = *reinterpret_cast<const float4*>(&qp[i]);
    }
    if (tid < T_) luts[tid] = g_lut[((size_t)bh * NB_ + n) * T_ + tid];
    __syncthreads();

    const int ty = tid >> 4, tx = tid & 15, r0 = ty * 4, c0 = tx * 4;
    float mrow[4], lrow[4], oacc[4][4];
#pragma unroll
    for (int i = 0; i < 4; i++) {
        mrow[i] = -3.4e38f; lrow[i] = 0.f;
#pragma unroll
        for (int j = 0; j < 4; j++) oacc[i][j] = 0.f;
    }

    for (int t = 0; t < T_; t++) {
        const float* kp = g_k + ((size_t)bh * L_ + luts[t] * 64) * D_;
        const float* vp = g_v + ((size_t)bh * L_ + luts[t] * 64) * D_;
#pragma unroll
        for (int i = tid * 4; i < 4096; i += 1024) {
            int r = i >> 6, d = i & 63;
            *reinterpret_cast<float4*>(&Ks[r * 68 + d]) = *reinterpret_cast<const float4*>(&kp[i]);
            *reinterpret_cast<float4*>(&Vs[r * 68 + d]) = *reinterpret_cast<const float4*>(&vp[i]);
        }
        __syncthreads();

        // S tile = scale * Q @ K^T   (4x4 per thread)
        float acc[4][4] = {};
#pragma unroll
        for (int d = 0; d < 64; d += 4) {
            float4 a[4], bv[4];
#pragma unroll
            for (int i = 0; i < 4; i++) a[i] = *reinterpret_cast<float4*>(&Qs[(r0 + i) * 68 + d]);
#pragma unroll
            for (int j = 0; j < 4; j++) bv[j] = *reinterpret_cast<float4*>(&Ks[(c0 + j) * 68 + d]);
#pragma unroll
            for (int i = 0; i < 4; i++)
#pragma unroll
                for (int j = 0; j < 4; j++)
                    acc[i][j] += a[i].x * bv[j].x + a[i].y * bv[j].y + a[i].z * bv[j].z + a[i].w * bv[j].w;
        }

        // online softmax update over the 64 new columns (row group = 16 lanes, same ty)
#pragma unroll
        for (int i = 0; i < 4; i++) {
            float rm = fmaxf(fmaxf(acc[i][0], acc[i][1]), fmaxf(acc[i][2], acc[i][3])) * 0.125f;
            rm = fmaxf(rm, __shfl_xor_sync(0xffffffffu, rm, 1));
            rm = fmaxf(rm, __shfl_xor_sync(0xffffffffu, rm, 2));
            rm = fmaxf(rm, __shfl_xor_sync(0xffffffffu, rm, 4));
            rm = fmaxf(rm, __shfl_xor_sync(0xffffffffu, rm, 8));
            float nm = fmaxf(mrow[i], rm);
            float corr = __expf(mrow[i] - nm);
            mrow[i] = nm;
            float rs = 0.f;
#pragma unroll
            for (int j = 0; j < 4; j++) {
                float p = __expf(acc[i][j] * 0.125f - nm);
                acc[i][j] = p;
                rs += p;
            }
            rs += __shfl_xor_sync(0xffffffffu, rs, 1);
            rs += __shfl_xor_sync(0xffffffffu, rs, 2);
            rs += __shfl_xor_sync(0xffffffffu, rs, 4);
            rs += __shfl_xor_sync(0xffffffffu, rs, 8);
            lrow[i] = lrow[i] * corr + rs;
#pragma unroll
            for (int j = 0; j < 4; j++) oacc[i][j] *= corr;
        }
        __syncthreads();           // all S reads of Ks done -> safe to overwrite with P

#pragma unroll
        for (int i = 0; i < 4; i++)
            *reinterpret_cast<float4*>(&Ks[(r0 + i) * 68 + c0]) =
                make_float4(acc[i][0], acc[i][1], acc[i][2], acc[i][3]);
        __syncthreads();

        // O += P @ V : P loads broadcast (ty-only), V loads contiguous (conflict-free)
#pragma unroll
        for (int kk = 0; kk < 64; kk += 4) {
            float4 pv[4], vv[4];
#pragma unroll
            for (int i = 0; i < 4; i++) pv[i] = *reinterpret_cast<float4*>(&Ks[(r0 + i) * 68 + kk]);
#pragma unroll
            for (int dd = 0; dd < 4; dd++) vv[dd] = *reinterpret_cast<float4*>(&Vs[(kk + dd) * 68 + c0]);
#pragma unroll
            for (int i = 0; i < 4; i++) {
                oacc[i][0] += pv[i].x * vv[0].x + pv[i].y * vv[1].x + pv[i].z * vv[2].x + pv[i].w * vv[3].x;
                oacc[i][1] += pv[i].x * vv[0].y + pv[i].y * vv[1].y + pv[i].z * vv[2].y + pv[i].w * vv[3].y;
                oacc[i][2] += pv[i].x * vv[0].z + pv[i].y * vv[1].z + pv[i].z * vv[2].z + pv[i].w * vv[3].z;
                oacc[i][3] += pv[i].x * vv[0].w + pv[i].y * vv[1].w + pv[i].z * vv[2].w + pv[i].w * vv[3].w;
            }
        }
        __syncthreads();           // before next t overwrites Ks/Vs
    }

    float* op = g_obuf + ((size_t)bh * L_ + n * 64) * D_;
#pragma unroll
    for (int i = 0; i < 4; i++) {
        float inv = 1.f / lrow[i];
        *reinterpret_cast<float4*>(&op[(r0 + i) * 64 + c0]) =
            make_float4(oacc[i][0] * inv, oacc[i][1] * inv, oacc[i][2] * inv, oacc[i][3] * inv);
    }
}

// ---------------- K5a: feature map = softmax over D for q and k ----------------
__global__ void k_featmap() {
    const int which = blockIdx.y;
    const float* src = which ? g_k : g_q;
    float* dst = which ? g_ck : g_cq;
    const int warp = threadIdx.x >> 5, lane = threadIdx.x & 31;
    const size_t row = (size_t)blockIdx.x * 8 + warp;
    const float* p = src + row * 64;
    float v0 = p[lane], v1 = p[lane + 32];
    float m = fmaxf(v0, v1);
#pragma unroll
    for (int o = 16; o; o >>= 1) m = fmaxf(m, __shfl_xor_sync(0xffffffffu, m, o));
    v0 = __expf(v0 - m); v1 = __expf(v1 - m);
    float s = v0 + v1;
#pragma unroll
    for (int o = 16; o; o >>= 1) s += __shfl_xor_sync(0xffffffffu, s, o);
    float inv = 1.f / s;
    dst[row * 64 + lane] = v0 * inv;
    dst[row * 64 + lane + 32] = v1 * inv;
}

// ---------------- K5b: per key block: kvb = cK^T @ V (DxD), ksum = colsum(cK) ----------------
__global__ void k_kvb() {
    __shared__ float CK[64][68];
    __shared__ float Vs[64][68];
    const int m = blockIdx.x, bh = blockIdx.y;
    const int tid = threadIdx.x;
    const float* ckp = g_ck + ((size_t)bh * L_ + m * 64) * D_;
    const float* vp  = g_v  + ((size_t)bh * L_ + m * 64) * D_;
    for (int i = tid * 4; i < 4096; i += 1024) {
        int r = i >> 6, d = i & 63;
        *reinterpret_cast<float4*>(&CK[r][d]) = *reinterpret_cast<const float4*>(&ckp[i]);
        *reinterpret_cast<float4*>(&Vs[r][d]) = *reinterpret_cast<const float4*>(&vp[i]);
    }
    __syncthreads();
    const int ty = tid >> 4, tx = tid & 15, d0 = ty * 4, e0 = tx * 4;
    float acc[4][4] = {};
    for (int k = 0; k < 64; k++) {
        float a[4];
#pragma unroll
        for (int i = 0; i < 4; i++) a[i] = CK[k][d0 + i];
        float4 bv = *reinterpret_cast<float4*>(&Vs[k][e0]);
#pragma unroll
        for (int i = 0; i < 4; i++) {
            acc[i][0] += a[i] * bv.x; acc[i][1] += a[i] * bv.y;
            acc[i][2] += a[i] * bv.z; acc[i][3] += a[i] * bv.w;
        }
    }
    float* dst = g_kvb + (size_t)(bh * NB_ + m) * D_ * D_;
#pragma unroll
    for (int i = 0; i < 4; i++)
        *reinterpret_cast<float4*>(&dst[(d0 + i) * 64 + e0]) =
            make_float4(acc[i][0], acc[i][1], acc[i][2], acc[i][3]);
    if (tid < 64) {
        float s = 0.f;
#pragma unroll 8
        for (int k = 0; k < 64; k++) s += CK[k][tid];
        g_ksum[(size_t)(bh * NB_ + m) * D_ + tid] = s;
    }
}

// ---------------- K5c: totals over all key blocks ----------------
__global__ void k_totals() {
    const int bh = blockIdx.x, tid = threadIdx.x;
    for (int i = tid; i < 4096; i += 256) {
        const float* p = g_kvb + (size_t)bh * NB_ * 4096 + i;
        float s = 0.f;
#pragma unroll 8
        for (int m = 0; m < 64; m++) s += p[(size_t)m * 4096];
        g_kvt[(size_t)bh * 4096 + i] = s;
    }
    if (tid < 64) {
        const float* p = g_ksum + (size_t)bh * NB_ * 64 + tid;
        float s = 0.f;
#pragma unroll 8
        for (int m = 0; m < 64; m++) s += p[m * 64];
        g_kst[bh * 64 + tid] = s;
    }
}

// ---------------- K5d: linear path per query block + proj_l, add into obuf ----------------
__global__ void k_linfinal(const float* __restrict__ plw, const float* __restrict__ plb) {
    __shared__ float A[64][68];   // KVQ (d,e) then OL (r,d)
    __shared__ float Bm[64][68];  // CQ (r,d) then PW (e,d)
    __shared__ float ksq[64], den_s[64];
    __shared__ int luts[T_];
    const int n = blockIdx.x, bh = blockIdx.y;
    const int tid = threadIdx.x;
    if (tid < T_) luts[tid] = g_lut[((size_t)bh * NB_ + n) * T_ + tid];
    __syncthreads();
    // kv_q = kv_total - sum of selected kvb (complement trick)
    for (int i = tid; i < 4096; i += 256) {
        float s = g_kvt[(size_t)bh * 4096 + i];
#pragma unroll
        for (int t = 0; t < T_; t++) s -= g_kvb[(size_t)(bh * NB_ + luts[t]) * 4096 + i];
        A[i >> 6][i & 63] = s;
    }
    if (tid < 64) {
        float s = g_kst[bh * 64 + tid];
#pragma unroll
        for (int t = 0; t < T_; t++) s -= g_ksum[(size_t)(bh * NB_ + luts[t]) * 64 + tid];
        ksq[tid] = s;
    }
    const float* cqp = g_cq + ((size_t)bh * L_ + n * 64) * D_;
    for (int i = tid * 4; i < 4096; i += 1024) {
        int r = i >> 6, d = i & 63;
        *reinterpret_cast<float4*>(&Bm[r][d]) = *reinterpret_cast<const float4*>(&cqp[i]);
    }
    __syncthreads();
    const int ty = tid >> 4, tx = tid & 15, r0 = ty * 4, c0 = tx * 4;
    float acc[4][4] = {};
    for (int d = 0; d < 64; d++) {
        float a[4];
#pragma unroll
        for (int i = 0; i < 4; i++) a[i] = Bm[r0 + i][d];
        float4 bv = *reinterpret_cast<float4*>(&A[d][c0]);
#pragma unroll
        for (int i = 0; i < 4; i++) {
            acc[i][0] += a[i] * bv.x; acc[i][1] += a[i] * bv.y;
            acc[i][2] += a[i] * bv.z; acc[i][3] += a[i] * bv.w;
        }
    }
    if (tid < 64) {
        float s = 0.f;
#pragma unroll 8
        for (int d = 0; d < 64; d++) s += Bm[tid][d] * ksq[d];
        den_s[tid] = s;
    }
    __syncthreads();
    // o_l -> A (overwrite KVQ)
#pragma unroll
    for (int i = 0; i < 4; i++) {
        float inv = 1.f / (den_s[r0 + i] + 1e-6f);
#pragma unroll
        for (int j = 0; j < 4; j++) A[r0 + i][c0 + j] = acc[i][j] * inv;
    }
    // PW -> Bm (overwrite CQ)
    for (int i = tid * 4; i < 4096; i += 1024) {
        int e = i >> 6, d = i & 63;
        *reinterpret_cast<float4*>(&Bm[e][d]) = *reinterpret_cast<const float4*>(&plw[i]);
    }
    __syncthreads();
    float acc2[4][4] = {};
    for (int d = 0; d < 64; d++) {
        float a[4], bb[4];
#pragma unroll
        for (int i = 0; i < 4; i++) a[i] = A[r0 + i][d];
#pragma unroll
        for (int j = 0; j < 4; j++) bb[j] = Bm[c0 + j][d];
#pragma unroll
        for (int i = 0; i < 4; i++)
#pragma unroll
            for (int j = 0; j < 4; j++) acc2[i][j] += a[i] * bb[j];
    }
    float pb0 = plb[c0], pb1 = plb[c0 + 1], pb2 = plb[c0 + 2], pb3 = plb[c0 + 3];
    float* op = g_obuf + ((size_t)bh * L_ + n * 64) * D_;
#pragma unroll
    for (int i = 0; i < 4; i++) {
        float4 v = *reinterpret_cast<float4*>(&op[(r0 + i) * 64 + c0]);
        v.x += acc2[i][0] + pb0; v.y += acc2[i][1] + pb1;
        v.z += acc2[i][2] + pb2; v.w += acc2[i][3] + pb3;
        *reinterpret_cast<float4*>(&op[(r0 + i) * 64 + c0]) = v;
    }
}

// ---------------- K6: out_proj GEMM, (256x256) @ (256,4096) per batch ----------------
__global__ void k_outproj(const float* __restrict__ w2, float* __restrict__ out) {
    __shared__ float As[16][68]; // [c][l]
    __shared__ float Ws[16][65]; // [c][co]
    const int l0 = blockIdx.x * 64, co0 = blockIdx.y * 64, b = blockIdx.z;
    const int tid = threadIdx.x;
    const int ty = tid >> 4, tx = tid & 15;
    float acc[4][4] = {};
    for (int c0 = 0; c0 < C_; c0 += 16) {
        const int h = c0 >> 6, d0 = c0 & 63;
        const float* ap = g_obuf + ((size_t)(b * NH_ + h) * L_ + l0) * D_ + d0;
        {   // load [l][d] 64x16, store transposed As[d][l]
            int i = tid * 4, l = i >> 4, d = i & 15;
            float4 v = *reinterpret_cast<const float4*>(&ap[(size_t)l * D_ + d]);
            As[d + 0][l] = v.x; As[d + 1][l] = v.y; As[d + 2][l] = v.z; As[d + 3][l] = v.w;
        }
        {
            int i = tid * 4, o = i >> 4, c = i & 15;
            float4 v = *reinterpret_cast<const float4*>(&w2[(size_t)(co0 + o) * C_ + c0 + c]);
            Ws[c + 0][o] = v.x; Ws[c + 1][o] = v.y; Ws[c + 2][o] = v.z; Ws[c + 3][o] = v.w;
        }
        __syncthreads();
#pragma unroll
        for (int c = 0; c < 16; c++) {
            float a[4], bb[4];
#pragma unroll
            for (int i = 0; i < 4; i++) a[i] = Ws[c][ty * 4 + i];   // co
#pragma unroll
            for (int j = 0; j < 4; j++) bb[j] = As[c][tx * 4 + j];  // l
#pragma unroll
            for (int i = 0; i < 4; i++)
#pragma unroll
                for (int j = 0; j < 4; j++) acc[i][j] += a[i] * bb[j];
        }
        __syncthreads();
    }
#pragma unroll
    for (int i = 0; i < 4; i++) {
        int co = co0 + ty * 4 + i;
        *reinterpret_cast<float4*>(&out[(size_t)b * C_ * L_ + (size_t)co * L_ + l0 + tx * 4]) =
            make_float4(acc[i][0], acc[i][1], acc[i][2], acc[i][3]);
    }
}

// ---------------- launch ----------------
extern "C" void kernel_launch(void* const* d_in, const int* in_sizes, int n_in,
                              void* d_out, int out_size) {
    const float* x     = (const float*)d_in[0];
    const float* qkv_w = (const float*)d_in[1];
    const float* out_w = (const float*)d_in[2];
    const float* plw   = (const float*)d_in[3];
    const float* plb   = (const float*)d_in[4];
    float* out = (float*)d_out;

    const int sattn_smem = 3 * 64 * 68 * (int)sizeof(float); // 52224 B
    cudaFuncSetAttribute(k_sattn, cudaFuncAttributeMaxDynamicSharedMemorySize, sattn_smem);

    k_qkv      <<<dim3(L_ / 64, 12, B_), 256>>>(x, qkv_w);
    k_blockmean<<<dim3(NB_, BH_, 2), 64>>>();
    k_topk     <<<BH_, 256>>>();
    k_sattn    <<<dim3(NB_, BH_), 256, sattn_smem>>>();
    k_featmap  <<<dim3(BH_ * L_ / 8, 2), 256>>>();
    k_kvb      <<<dim3(NB_, BH_), 256>>>();
    k_totals   <<<BH_, 256>>>();
    k_linfinal <<<dim3(NB_, BH_), 256>>>(plw, plb);
    k_outproj  <<<dim3(L_ / 64, C_ / 64, B_), 256>>>(out_w, out);
}

// round 3
// speedup vs baseline: 1.3527x; 1.1932x over previous
#include <cuda_runtime.h>

#define B_ 8
#define C_ 256
#define L_ 4096
#define NH_ 4
#define D_ 64
#define NB_ 64   // number of query/key blocks (L/64)
#define T_ 6     // top-k blocks
#define BH_ 32   // B*NH

// ---------------- scratch (device globals; no allocs) ----------------
__device__ float g_q [BH_*L_*D_];
__device__ float g_k [BH_*L_*D_];
__device__ float g_v [BH_*L_*D_];
__device__ float g_cq[BH_*L_*D_];
__device__ float g_ck[BH_*L_*D_];
__device__ float g_qb[BH_*NB_*D_];
__device__ float g_kb[BH_*NB_*D_];
__device__ int   g_lut[BH_*NB_*T_];
__device__ float g_kvb[(size_t)BH_*NB_*D_*D_];
__device__ float g_ksum[BH_*NB_*D_];
__device__ float g_kvt[BH_*D_*D_];
__device__ float g_kst[BH_*D_];
__device__ float g_obuf[BH_*L_*D_];

// ---------------- K1: qkv = W(768x256) @ X(256,4096), write q/k/v as (B,NH,L,D) ----------------
__global__ void k_qkv(const float* __restrict__ x, const float* __restrict__ w) {
    __shared__ float Xs[16][64];
    __shared__ float Ws[16][64];
    const int b  = blockIdx.z;
    const int l0 = blockIdx.x * 64;
    const int o0 = blockIdx.y * 64;
    const int tid = threadIdx.x;
    const int ty = tid >> 4, tx = tid & 15;
    float acc[4][4] = {};
    const float* xb = x + (size_t)b * C_ * L_;
    for (int c0 = 0; c0 < C_; c0 += 16) {
        {   // X tile [c][l], 16x64
            int i = tid * 4, c = i >> 6, l = i & 63;
            float4 v = *reinterpret_cast<const float4*>(&xb[(size_t)(c0 + c) * L_ + l0 + l]);
            *reinterpret_cast<float4*>(&Xs[c][l]) = v;
        }
        {   // W tile, stored transposed as Ws[c][o]
            int i = tid * 4, o = i >> 4, c = i & 15;
            float4 v = *reinterpret_cast<const float4*>(&w[(size_t)(o0 + o) * C_ + c0 + c]);
            Ws[c + 0][o] = v.x; Ws[c + 1][o] = v.y; Ws[c + 2][o] = v.z; Ws[c + 3][o] = v.w;
        }
        __syncthreads();
#pragma unroll
        for (int c = 0; c < 16; c++) {
            float4 a  = *reinterpret_cast<float4*>(&Xs[c][ty * 4]);
            float4 bb = *reinterpret_cast<float4*>(&Ws[c][tx * 4]);
            float av[4] = {a.x, a.y, a.z, a.w};
            float bv[4] = {bb.x, bb.y, bb.z, bb.w};
#pragma unroll
            for (int i = 0; i < 4; i++)
#pragma unroll
                for (int j = 0; j < 4; j++) acc[i][j] += av[i] * bv[j];
        }
        __syncthreads();
    }
    const int part = o0 >> 8, h = (o0 >> 6) & 3;
    float* dst = (part == 0) ? g_q : (part == 1) ? g_k : g_v;
    dst += (size_t)(b * NH_ + h) * L_ * D_;
#pragma unroll
    for (int i = 0; i < 4; i++) {
        int l = l0 + ty * 4 + i;
        *reinterpret_cast<float4*>(&dst[(size_t)l * D_ + tx * 4]) =
            make_float4(acc[i][0], acc[i][1], acc[i][2], acc[i][3]);
    }
}

// ---------------- K2: per-block token means qb/kb ----------------
__global__ void k_blockmean() {
    const int n = blockIdx.x, bh = blockIdx.y, which = blockIdx.z;
    const float* src = which ? g_k : g_q;
    float* dst = which ? g_kb : g_qb;
    const int d = threadIdx.x;
    const float* p = src + ((size_t)bh * L_ + n * 64) * D_;
    float s = 0.f;
#pragma unroll 8
    for (int i = 0; i < 64; i++) s += p[i * D_ + d];
    dst[((size_t)bh * NB_ + n) * D_ + d] = s * (1.f / 64.f);
}

// ---------------- K3: block scores + top-6 (ties -> lowest index) ----------------
__global__ void k_topk() {
    __shared__ float QB[64][64];
    __shared__ float KB[64][64];
    __shared__ float S[64][64];
    const int bh = blockIdx.x;
    for (int i = threadIdx.x; i < 4096; i += 256) {
        QB[i >> 6][i & 63] = g_qb[(size_t)bh * 4096 + i];
        KB[i >> 6][i & 63] = g_kb[(size_t)bh * 4096 + i];
    }
    __syncthreads();
    const int r = threadIdx.x >> 2, cb = (threadIdx.x & 3) * 16;
    for (int c = cb; c < cb + 16; c++) {
        float s = 0.f;
#pragma unroll 8
        for (int d = 0; d < 64; d++) s += QB[r][d] * KB[c][d];
        S[r][c] = s;
    }
    __syncthreads();
    if (threadIdx.x < 64) {
        const int rr = threadIdx.x;
        unsigned long long used = 0ull;
        for (int t = 0; t < T_; t++) {
            float best = -3.4e38f; int bi = 0;
            for (int c = 0; c < 64; c++) {
                if ((used >> c) & 1ull) continue;
                float v = S[rr][c];
                if (v > best) { best = v; bi = c; }
            }
            used |= 1ull << bi;
            g_lut[((size_t)bh * NB_ + rr) * T_ + t] = bi;
        }
    }
}

// ---------------- K4: sparse attention, flash-style, K stored TRANSPOSED ----------------
// smem: Qs[64][68] | Kt[64][68] (K^T tile; reused for P row-major) | Vs[64][68]
__global__ void __launch_bounds__(256, 4) k_sattn() {
    extern __shared__ float sm[];
    float* Qs = sm;               // Q row-major [r][d], stride 68
    float* Kt = sm + 64 * 68;     // K transposed [d][r], stride 68; later P [r][c]
    float* Vs = sm + 2 * 64 * 68; // V row-major [r][d], stride 68
    __shared__ int luts[T_];
    const int n = blockIdx.x, bh = blockIdx.y;
    const int tid = threadIdx.x;
    const float* qp = g_q + ((size_t)bh * L_ + n * 64) * D_;
#pragma unroll
    for (int i = tid * 4; i < 4096; i += 1024) {
        int r = i >> 6, d = i & 63;
        *reinterpret_cast<float4*>(&Qs[r * 68 + d]) = *reinterpret_cast<const float4*>(&qp[i]);
    }
    if (tid < T_) luts[tid] = g_lut[((size_t)bh * NB_ + n) * T_ + tid];
    __syncthreads();

    const int ty = tid >> 4, tx = tid & 15, r0 = ty * 4, c0 = tx * 4;
    float mrow[4], lrow[4], oacc[4][4];
#pragma unroll
    for (int i = 0; i < 4; i++) {
        mrow[i] = -3.4e38f; lrow[i] = 0.f;
#pragma unroll
        for (int j = 0; j < 4; j++) oacc[i][j] = 0.f;
    }

    const int lr = tid & 15, ld4 = (tid >> 4) * 4;   // transpose-load mapping (conflict-free STS)

    for (int t = 0; t < T_; t++) {
        const float* kp = g_k + ((size_t)bh * L_ + luts[t] * 64) * D_;
        const float* vp = g_v + ((size_t)bh * L_ + luts[t] * 64) * D_;
#pragma unroll
        for (int rep = 0; rep < 4; rep++) {
            int r = lr + rep * 16;
            float4 kv = *reinterpret_cast<const float4*>(&kp[r * 64 + ld4]);
            Kt[(ld4 + 0) * 68 + r] = kv.x;
            Kt[(ld4 + 1) * 68 + r] = kv.y;
            Kt[(ld4 + 2) * 68 + r] = kv.z;
            Kt[(ld4 + 3) * 68 + r] = kv.w;
        }
#pragma unroll
        for (int i = tid * 4; i < 4096; i += 1024) {
            int r = i >> 6, d = i & 63;
            *reinterpret_cast<float4*>(&Vs[r * 68 + d]) = *reinterpret_cast<const float4*>(&vp[i]);
        }
        __syncthreads();

        // S tile = Q @ K^T : A from Qs (broadcast), B from Kt (contiguous float4)
        float acc[4][4] = {};
#pragma unroll
        for (int d = 0; d < 64; d += 4) {
            float4 a[4], kt[4];
#pragma unroll
            for (int i = 0; i < 4; i++) a[i] = *reinterpret_cast<float4*>(&Qs[(r0 + i) * 68 + d]);
#pragma unroll
            for (int dd = 0; dd < 4; dd++) kt[dd] = *reinterpret_cast<float4*>(&Kt[(d + dd) * 68 + c0]);
#pragma unroll
            for (int i = 0; i < 4; i++) {
                acc[i][0] += a[i].x * kt[0].x + a[i].y * kt[1].x + a[i].z * kt[2].x + a[i].w * kt[3].x;
                acc[i][1] += a[i].x * kt[0].y + a[i].y * kt[1].y + a[i].z * kt[2].y + a[i].w * kt[3].y;
                acc[i][2] += a[i].x * kt[0].z + a[i].y * kt[1].z + a[i].z * kt[2].z + a[i].w * kt[3].z;
                acc[i][3] += a[i].x * kt[0].w + a[i].y * kt[1].w + a[i].z * kt[2].w + a[i].w * kt[3].w;
            }
        }

        // online softmax over the 64 new columns (row group = 16 lanes, same ty)
#pragma unroll
        for (int i = 0; i < 4; i++) {
            float rm = fmaxf(fmaxf(acc[i][0], acc[i][1]), fmaxf(acc[i][2], acc[i][3])) * 0.125f;
            rm = fmaxf(rm, __shfl_xor_sync(0xffffffffu, rm, 1));
            rm = fmaxf(rm, __shfl_xor_sync(0xffffffffu, rm, 2));
            rm = fmaxf(rm, __shfl_xor_sync(0xffffffffu, rm, 4));
            rm = fmaxf(rm, __shfl_xor_sync(0xffffffffu, rm, 8));
            float nm = fmaxf(mrow[i], rm);
            float corr = __expf(mrow[i] - nm);
            mrow[i] = nm;
            float rs = 0.f;
#pragma unroll
            for (int j = 0; j < 4; j++) {
                float p = __expf(acc[i][j] * 0.125f - nm);
                acc[i][j] = p;
                rs += p;
            }
            rs += __shfl_xor_sync(0xffffffffu, rs, 1);
            rs += __shfl_xor_sync(0xffffffffu, rs, 2);
            rs += __shfl_xor_sync(0xffffffffu, rs, 4);
            rs += __shfl_xor_sync(0xffffffffu, rs, 8);
            lrow[i] = lrow[i] * corr + rs;
#pragma unroll
            for (int j = 0; j < 4; j++) oacc[i][j] *= corr;
        }
        __syncthreads();           // S reads of Kt done -> safe to overwrite with P

#pragma unroll
        for (int i = 0; i < 4; i++)
            *reinterpret_cast<float4*>(&Kt[(r0 + i) * 68 + c0]) =
                make_float4(acc[i][0], acc[i][1], acc[i][2], acc[i][3]);
        __syncthreads();

        // O += P @ V : P broadcast (ty-only), V contiguous float4
#pragma unroll
        for (int kk = 0; kk < 64; kk += 4) {
            float4 pv[4], vv[4];
#pragma unroll
            for (int i = 0; i < 4; i++) pv[i] = *reinterpret_cast<float4*>(&Kt[(r0 + i) * 68 + kk]);
#pragma unroll
            for (int dd = 0; dd < 4; dd++) vv[dd] = *reinterpret_cast<float4*>(&Vs[(kk + dd) * 68 + c0]);
#pragma unroll
            for (int i = 0; i < 4; i++) {
                oacc[i][0] += pv[i].x * vv[0].x + pv[i].y * vv[1].x + pv[i].z * vv[2].x + pv[i].w * vv[3].x;
                oacc[i][1] += pv[i].x * vv[0].y + pv[i].y * vv[1].y + pv[i].z * vv[2].y + pv[i].w * vv[3].y;
                oacc[i][2] += pv[i].x * vv[0].z + pv[i].y * vv[1].z + pv[i].z * vv[2].z + pv[i].w * vv[3].z;
                oacc[i][3] += pv[i].x * vv[0].w + pv[i].y * vv[1].w + pv[i].z * vv[2].w + pv[i].w * vv[3].w;
            }
        }
        __syncthreads();           // before next t overwrites Kt/Vs
    }

    float* op = g_obuf + ((size_t)bh * L_ + n * 64) * D_;
#pragma unroll
    for (int i = 0; i < 4; i++) {
        float inv = 1.f / lrow[i];
        *reinterpret_cast<float4*>(&op[(r0 + i) * 64 + c0]) =
            make_float4(oacc[i][0] * inv, oacc[i][1] * inv, oacc[i][2] * inv, oacc[i][3] * inv);
    }
}

// ---------------- K5a: feature map = softmax over D for q and k ----------------
__global__ void k_featmap() {
    const int which = blockIdx.y;
    const float* src = which ? g_k : g_q;
    float* dst = which ? g_ck : g_cq;
    const int warp = threadIdx.x >> 5, lane = threadIdx.x & 31;
    const size_t row = (size_t)blockIdx.x * 8 + warp;
    const float* p = src + row * 64;
    float v0 = p[lane], v1 = p[lane + 32];
    float m = fmaxf(v0, v1);
#pragma unroll
    for (int o = 16; o; o >>= 1) m = fmaxf(m, __shfl_xor_sync(0xffffffffu, m, o));
    v0 = __expf(v0 - m); v1 = __expf(v1 - m);
    float s = v0 + v1;
#pragma unroll
    for (int o = 16; o; o >>= 1) s += __shfl_xor_sync(0xffffffffu, s, o);
    float inv = 1.f / s;
    dst[row * 64 + lane] = v0 * inv;
    dst[row * 64 + lane + 32] = v1 * inv;
}

// ---------------- K5b: per key block: kvb = cK^T @ V (DxD), ksum = colsum(cK) ----------------
__global__ void k_kvb() {
    __shared__ float CK[64][68];
    __shared__ float Vs[64][68];
    const int m = blockIdx.x, bh = blockIdx.y;
    const int tid = threadIdx.x;
    const float* ckp = g_ck + ((size_t)bh * L_ + m * 64) * D_;
    const float* vp  = g_v  + ((size_t)bh * L_ + m * 64) * D_;
    for (int i = tid * 4; i < 4096; i += 1024) {
        int r = i >> 6, d = i & 63;
        *reinterpret_cast<float4*>(&CK[r][d]) = *reinterpret_cast<const float4*>(&ckp[i]);
        *reinterpret_cast<float4*>(&Vs[r][d]) = *reinterpret_cast<const float4*>(&vp[i]);
    }
    __syncthreads();
    const int ty = tid >> 4, tx = tid & 15, d0 = ty * 4, e0 = tx * 4;
    float acc[4][4] = {};
    for (int k = 0; k < 64; k++) {
        float4 a4 = *reinterpret_cast<float4*>(&CK[k][d0]);
        float a[4] = {a4.x, a4.y, a4.z, a4.w};
        float4 bv = *reinterpret_cast<float4*>(&Vs[k][e0]);
#pragma unroll
        for (int i = 0; i < 4; i++) {
            acc[i][0] += a[i] * bv.x; acc[i][1] += a[i] * bv.y;
            acc[i][2] += a[i] * bv.z; acc[i][3] += a[i] * bv.w;
        }
    }
    float* dst = g_kvb + (size_t)(bh * NB_ + m) * D_ * D_;
#pragma unroll
    for (int i = 0; i < 4; i++)
        *reinterpret_cast<float4*>(&dst[(d0 + i) * 64 + e0]) =
            make_float4(acc[i][0], acc[i][1], acc[i][2], acc[i][3]);
    if (tid < 64) {
        float s = 0.f;
#pragma unroll 8
        for (int k = 0; k < 64; k++) s += CK[k][tid];
        g_ksum[(size_t)(bh * NB_ + m) * D_ + tid] = s;
    }
}

// ---------------- K5c: totals over all key blocks ----------------
__global__ void k_totals() {
    const int bh = blockIdx.x, tid = threadIdx.x;
    for (int i = tid; i < 4096; i += 256) {
        const float* p = g_kvb + (size_t)bh * NB_ * 4096 + i;
        float s = 0.f;
#pragma unroll 8
        for (int m = 0; m < 64; m++) s += p[(size_t)m * 4096];
        g_kvt[(size_t)bh * 4096 + i] = s;
    }
    if (tid < 64) {
        const float* p = g_ksum + (size_t)bh * NB_ * 64 + tid;
        float s = 0.f;
#pragma unroll 8
        for (int m = 0; m < 64; m++) s += p[m * 64];
        g_kst[bh * 64 + tid] = s;
    }
}

// ---------------- K5d: linear path per query block + proj_l, add into obuf ----------------
__global__ void k_linfinal(const float* __restrict__ plw, const float* __restrict__ plb) {
    __shared__ float A[64][68];   // KVQ (d,e) then OL (r,d)
    __shared__ float Bm[64][68];  // CQ (r,d) then PW (e,d)
    __shared__ float ksq[64], den_s[64];
    __shared__ int luts[T_];
    const int n = blockIdx.x, bh = blockIdx.y;
    const int tid = threadIdx.x;
    if (tid < T_) luts[tid] = g_lut[((size_t)bh * NB_ + n) * T_ + tid];
    __syncthreads();
    // kv_q = kv_total - sum of selected kvb (complement trick)
    for (int i = tid; i < 4096; i += 256) {
        float s = g_kvt[(size_t)bh * 4096 + i];
#pragma unroll
        for (int t = 0; t < T_; t++) s -= g_kvb[(size_t)(bh * NB_ + luts[t]) * 4096 + i];
        A[i >> 6][i & 63] = s;
    }
    if (tid < 64) {
        float s = g_kst[bh * 64 + tid];
#pragma unroll
        for (int t = 0; t < T_; t++) s -= g_ksum[(size_t)(bh * NB_ + luts[t]) * 64 + tid];
        ksq[tid] = s;
    }
    const float* cqp = g_cq + ((size_t)bh * L_ + n * 64) * D_;
    for (int i = tid * 4; i < 4096; i += 1024) {
        int r = i >> 6, d = i & 63;
        *reinterpret_cast<float4*>(&Bm[r][d]) = *reinterpret_cast<const float4*>(&cqp[i]);
    }
    __syncthreads();
    const int ty = tid >> 4, tx = tid & 15, r0 = ty * 4, c0 = tx * 4;
    float acc[4][4] = {};
    for (int d = 0; d < 64; d++) {
        float a[4];
#pragma unroll
        for (int i = 0; i < 4; i++) a[i] = Bm[r0 + i][d];
        float4 bv = *reinterpret_cast<float4*>(&A[d][c0]);
#pragma unroll
        for (int i = 0; i < 4; i++) {
            acc[i][0] += a[i] * bv.x; acc[i][1] += a[i] * bv.y;
            acc[i][2] += a[i] * bv.z; acc[i][3] += a[i] * bv.w;
        }
    }
    if (tid < 64) {
        float s = 0.f;
#pragma unroll 8
        for (int d = 0; d < 64; d++) s += Bm[tid][d] * ksq[d];
        den_s[tid] = s;
    }
    __syncthreads();
    // o_l -> A (overwrite KVQ)
#pragma unroll
    for (int i = 0; i < 4; i++) {
        float inv = 1.f / (den_s[r0 + i] + 1e-6f);
#pragma unroll
        for (int j = 0; j < 4; j++) A[r0 + i][c0 + j] = acc[i][j] * inv;
    }
    // PW -> Bm (overwrite CQ)
    for (int i = tid * 4; i < 4096; i += 1024) {
        int e = i >> 6, d = i & 63;
        *reinterpret_cast<float4*>(&Bm[e][d]) = *reinterpret_cast<const float4*>(&plw[i]);
    }
    __syncthreads();
    float acc2[4][4] = {};
    for (int d = 0; d < 64; d++) {
        float a[4], bb[4];
#pragma unroll
        for (int i = 0; i < 4; i++) a[i] = A[r0 + i][d];
#pragma unroll
        for (int j = 0; j < 4; j++) bb[j] = Bm[c0 + j][d];
#pragma unroll
        for (int i = 0; i < 4; i++)
#pragma unroll
            for (int j = 0; j < 4; j++) acc2[i][j] += a[i] * bb[j];
    }
    float pb0 = plb[c0], pb1 = plb[c0 + 1], pb2 = plb[c0 + 2], pb3 = plb[c0 + 3];
    float* op = g_obuf + ((size_t)bh * L_ + n * 64) * D_;
#pragma unroll
    for (int i = 0; i < 4; i++) {
        float4 v = *reinterpret_cast<float4*>(&op[(r0 + i) * 64 + c0]);
        v.x += acc2[i][0] + pb0; v.y += acc2[i][1] + pb1;
        v.z += acc2[i][2] + pb2; v.w += acc2[i][3] + pb3;
        *reinterpret_cast<float4*>(&op[(r0 + i) * 64 + c0]) = v;
    }
}

// ---------------- K6: out_proj GEMM, (256x256) @ (256,4096) per batch ----------------
__global__ void k_outproj(const float* __restrict__ w2, float* __restrict__ out) {
    __shared__ float As[16][68]; // [c][l]
    __shared__ float Ws[16][64]; // [c][co]
    const int l0 = blockIdx.x * 64, co0 = blockIdx.y * 64, b = blockIdx.z;
    const int tid = threadIdx.x;
    const int ty = tid >> 4, tx = tid & 15;
    float acc[4][4] = {};
    for (int c0 = 0; c0 < C_; c0 += 16) {
        const int h = c0 >> 6, d0 = c0 & 63;
        const float* ap = g_obuf + ((size_t)(b * NH_ + h) * L_ + l0) * D_ + d0;
        {   // load [l][d] 64x16, store transposed As[d][l]
            int i = tid * 4, l = i >> 4, d = i & 15;
            float4 v = *reinterpret_cast<const float4*>(&ap[(size_t)l * D_ + d]);
            As[d + 0][l] = v.x; As[d + 1][l] = v.y; As[d + 2][l] = v.z; As[d + 3][l] = v.w;
        }
        {
            int i = tid * 4, o = i >> 4, c = i & 15;
            float4 v = *reinterpret_cast<const float4*>(&w2[(size_t)(co0 + o) * C_ + c0 + c]);
            Ws[c + 0][o] = v.x; Ws[c + 1][o] = v.y; Ws[c + 2][o] = v.z; Ws[c + 3][o] = v.w;
        }
        __syncthreads();
#pragma unroll
        for (int c = 0; c < 16; c++) {
            float4 a4 = *reinterpret_cast<float4*>(&Ws[c][ty * 4]);   // co
            float4 b4 = *reinterpret_cast<float4*>(&As[c][tx * 4]);   // l
            float a[4] = {a4.x, a4.y, a4.z, a4.w};
            float bb[4] = {b4.x, b4.y, b4.z, b4.w};
#pragma unroll
            for (int i = 0; i < 4; i++)
#pragma unroll
                for (int j = 0; j < 4; j++) acc[i][j] += a[i] * bb[j];
        }
        __syncthreads();
    }
#pragma unroll
    for (int i = 0; i < 4; i++) {
        int co = co0 + ty * 4 + i;
        *reinterpret_cast<float4*>(&out[(size_t)b * C_ * L_ + (size_t)co * L_ + l0 + tx * 4]) =
            make_float4(acc[i][0], acc[i][1], acc[i][2], acc[i][3]);
    }
}

// ---------------- launch ----------------
extern "C" void kernel_launch(void* const* d_in, const int* in_sizes, int n_in,
                              void* d_out, int out_size) {
    const float* x     = (const float*)d_in[0];
    const float* qkv_w = (const float*)d_in[1];
    const float* out_w = (const float*)d_in[2];
    const float* plw   = (const float*)d_in[3];
    const float* plb   = (const float*)d_in[4];
    float* out = (float*)d_out;

    const int sattn_smem = 3 * 64 * 68 * (int)sizeof(float); // 52224 B
    cudaFuncSetAttribute(k_sattn, cudaFuncAttributeMaxDynamicSharedMemorySize, sattn_smem);

    k_qkv      <<<dim3(L_ / 64, 12, B_), 256>>>(x, qkv_w);
    k_blockmean<<<dim3(NB_, BH_, 2), 64>>>();
    k_topk     <<<BH_, 256>>>();
    k_sattn    <<<dim3(NB_, BH_), 256, sattn_smem>>>();
    k_featmap  <<<dim3(BH_ * L_ / 8, 2), 256>>>();
    k_kvb      <<<dim3(NB_, BH_), 256>>>();
    k_totals   <<<BH_, 256>>>();
    k_linfinal <<<dim3(NB_, BH_), 256>>>(plw, plb);
    k_outproj  <<<dim3(L_ / 64, C_ / 64, B_), 256>>>(out_w, out);
}

// round 4
// speedup vs baseline: 1.7248x; 1.2752x over previous
#include <cuda_runtime.h>

#define B_ 8
#define C_ 256
#define L_ 4096
#define NH_ 4
#define D_ 64
#define NB_ 64   // number of query/key blocks (L/64)
#define T_ 6     // top-k blocks
#define BH_ 32   // B*NH

// ---------------- scratch (device globals; no allocs) ----------------
__device__ float g_q [BH_*L_*D_];
__device__ float g_k [BH_*L_*D_];
__device__ float g_v [BH_*L_*D_];
__device__ float g_cq[BH_*L_*D_];
__device__ float g_ck[BH_*L_*D_];
__device__ float g_qb[BH_*NB_*D_];
__device__ float g_kb[BH_*NB_*D_];
__device__ int   g_lut[BH_*NB_*T_];
__device__ float g_kvb[(size_t)BH_*NB_*D_*D_];
__device__ float g_ksum[BH_*NB_*D_];
__device__ float g_kvt[BH_*D_*D_];
__device__ float g_kst[BH_*D_];
__device__ float g_obuf[BH_*L_*D_];

// ---------------- tf32 mma helpers ----------------
__device__ __forceinline__ unsigned f2tf(float f) {
    unsigned u; asm("cvt.rna.tf32.f32 %0, %1;" : "=r"(u) : "f"(f)); return u;
}
__device__ __forceinline__ void mma8(float d[4], const unsigned a[4], const unsigned b[2]) {
    asm("mma.sync.aligned.m16n8k8.row.col.f32.tf32.tf32.f32 "
        "{%0,%1,%2,%3}, {%4,%5,%6,%7}, {%8,%9}, {%0,%1,%2,%3};"
        : "+f"(d[0]), "+f"(d[1]), "+f"(d[2]), "+f"(d[3])
        : "r"(a[0]), "r"(a[1]), "r"(a[2]), "r"(a[3]), "r"(b[0]), "r"(b[1]));
}

// ---------------- K1: qkv = W(768x256) @ X(256,4096), write q/k/v as (B,NH,L,D) ----------------
__global__ void k_qkv(const float* __restrict__ x, const float* __restrict__ w) {
    __shared__ float Xs[16][64];
    __shared__ float Ws[16][64];
    const int b  = blockIdx.z;
    const int l0 = blockIdx.x * 64;
    const int o0 = blockIdx.y * 64;
    const int tid = threadIdx.x;
    const int ty = tid >> 4, tx = tid & 15;
    float acc[4][4] = {};
    const float* xb = x + (size_t)b * C_ * L_;
    for (int c0 = 0; c0 < C_; c0 += 16) {
        {
            int i = tid * 4, c = i >> 6, l = i & 63;
            float4 v = *reinterpret_cast<const float4*>(&xb[(size_t)(c0 + c) * L_ + l0 + l]);
            *reinterpret_cast<float4*>(&Xs[c][l]) = v;
        }
        {
            int i = tid * 4, o = i >> 4, c = i & 15;
            float4 v = *reinterpret_cast<const float4*>(&w[(size_t)(o0 + o) * C_ + c0 + c]);
            Ws[c + 0][o] = v.x; Ws[c + 1][o] = v.y; Ws[c + 2][o] = v.z; Ws[c + 3][o] = v.w;
        }
        __syncthreads();
#pragma unroll
        for (int c = 0; c < 16; c++) {
            float4 a  = *reinterpret_cast<float4*>(&Xs[c][ty * 4]);
            float4 bb = *reinterpret_cast<float4*>(&Ws[c][tx * 4]);
            float av[4] = {a.x, a.y, a.z, a.w};
            float bv[4] = {bb.x, bb.y, bb.z, bb.w};
#pragma unroll
            for (int i = 0; i < 4; i++)
#pragma unroll
                for (int j = 0; j < 4; j++) acc[i][j] += av[i] * bv[j];
        }
        __syncthreads();
    }
    const int part = o0 >> 8, h = (o0 >> 6) & 3;
    float* dst = (part == 0) ? g_q : (part == 1) ? g_k : g_v;
    dst += (size_t)(b * NH_ + h) * L_ * D_;
#pragma unroll
    for (int i = 0; i < 4; i++) {
        int l = l0 + ty * 4 + i;
        *reinterpret_cast<float4*>(&dst[(size_t)l * D_ + tx * 4]) =
            make_float4(acc[i][0], acc[i][1], acc[i][2], acc[i][3]);
    }
}

// ---------------- K2: per-block token means qb/kb ----------------
__global__ void k_blockmean() {
    const int n = blockIdx.x, bh = blockIdx.y, which = blockIdx.z;
    const float* src = which ? g_k : g_q;
    float* dst = which ? g_kb : g_qb;
    const int d = threadIdx.x;
    const float* p = src + ((size_t)bh * L_ + n * 64) * D_;
    float s = 0.f;
#pragma unroll 8
    for (int i = 0; i < 64; i++) s += p[i * D_ + d];
    dst[((size_t)bh * NB_ + n) * D_ + d] = s * (1.f / 64.f);
}

// ---------------- K3: block scores + top-6 (ties -> lowest index) ----------------
__global__ void k_topk() {
    __shared__ float QB[64][64];
    __shared__ float KB[64][64];
    __shared__ float S[64][64];
    const int bh = blockIdx.x;
    for (int i = threadIdx.x; i < 4096; i += 256) {
        QB[i >> 6][i & 63] = g_qb[(size_t)bh * 4096 + i];
        KB[i >> 6][i & 63] = g_kb[(size_t)bh * 4096 + i];
    }
    __syncthreads();
    const int r = threadIdx.x >> 2, cb = (threadIdx.x & 3) * 16;
    for (int c = cb; c < cb + 16; c++) {
        float s = 0.f;
#pragma unroll 8
        for (int d = 0; d < 64; d++) s += QB[r][d] * KB[c][d];
        S[r][c] = s;
    }
    __syncthreads();
    if (threadIdx.x < 64) {
        const int rr = threadIdx.x;
        unsigned long long used = 0ull;
        for (int t = 0; t < T_; t++) {
            float best = -3.4e38f; int bi = 0;
            for (int c = 0; c < 64; c++) {
                if ((used >> c) & 1ull) continue;
                float v = S[rr][c];
                if (v > best) { best = v; bi = c; }
            }
            used |= 1ull << bi;
            g_lut[((size_t)bh * NB_ + rr) * T_ + t] = bi;
        }
    }
}

// ---------------- K4: sparse attention, tf32 mma.sync flash-style ----------------
// dyn smem (floats): Qs[64*68] | Ks[64*68] (K tile then P) | Vs[64*72] | redm[2*64] | reds[2*64]
#define QS_OFF 0
#define KS_OFF (64*68)
#define VS_OFF (2*64*68)
#define RM_OFF (2*64*68 + 64*72)
#define RS_OFF (RM_OFF + 2*64)
#define SATTN_SMEM_FLOATS (RS_OFF + 2*64)

__global__ void __launch_bounds__(256, 3) k_sattn() {
    extern __shared__ float sm[];
    float* Qs = sm + QS_OFF;
    float* Ks = sm + KS_OFF;   // K tile, later P tile
    float* Vs = sm + VS_OFF;
    float* redm = sm + RM_OFF;
    float* reds = sm + RS_OFF;
    __shared__ int luts[8];
    const int n = blockIdx.x, bh = blockIdx.y;
    const int tid = threadIdx.x;
    const int w = tid >> 5, lane = tid & 31;
    const int gid = lane >> 2, tig = lane & 3;
    const int m0 = (w >> 1) * 16;     // row base (16 rows per warp)
    const int ch = w & 1;             // column half
    const int n0c = ch * 32;

    const float* qp = g_q + ((size_t)bh * L_ + n * 64) * D_;
    for (int i = tid * 4; i < 4096; i += 1024) {
        int r = i >> 6, d = i & 63;
        *reinterpret_cast<float4*>(&Qs[r * 68 + d]) = *reinterpret_cast<const float4*>(&qp[i]);
    }
    if (tid < T_) luts[tid] = g_lut[((size_t)bh * NB_ + n) * T_ + tid];
    __syncthreads();

    float oacc[4][4] = {};            // [ntile j][reg]; rows gid / gid+8, cols n0c+8j+2tig(+1)
    float m_a = -1e30f, m_b = -1e30f, l_a = 0.f, l_b = 0.f;
    const int ra = m0 + gid, rb = m0 + gid + 8;

    for (int t = 0; t < T_; t++) {
        const float* kp = g_k + ((size_t)bh * L_ + luts[t] * 64) * D_;
        const float* vp = g_v + ((size_t)bh * L_ + luts[t] * 64) * D_;
        for (int i = tid * 4; i < 4096; i += 1024) {
            int r = i >> 6, d = i & 63;
            *reinterpret_cast<float4*>(&Ks[r * 68 + d]) = *reinterpret_cast<const float4*>(&kp[i]);
            *reinterpret_cast<float4*>(&Vs[r * 72 + d]) = *reinterpret_cast<const float4*>(&vp[i]);
        }
        __syncthreads();

        // ---- S = Q @ K^T (this warp: rows m0..m0+15, cols n0c..n0c+31) ----
        float sacc[4][4] = {};
#pragma unroll
        for (int kk = 0; kk < 64; kk += 8) {
            unsigned a[4];
            a[0] = f2tf(Qs[ra * 68 + kk + tig]);
            a[1] = f2tf(Qs[rb * 68 + kk + tig]);
            a[2] = f2tf(Qs[ra * 68 + kk + tig + 4]);
            a[3] = f2tf(Qs[rb * 68 + kk + tig + 4]);
#pragma unroll
            for (int j = 0; j < 4; j++) {
                unsigned b[2];
                b[0] = f2tf(Ks[(n0c + 8 * j + gid) * 68 + kk + tig]);
                b[1] = f2tf(Ks[(n0c + 8 * j + gid) * 68 + kk + tig + 4]);
                mma8(sacc[j], a, b);
            }
        }
#pragma unroll
        for (int j = 0; j < 4; j++)
#pragma unroll
            for (int r = 0; r < 4; r++) sacc[j][r] *= 0.125f;

        // ---- online softmax: warp-level row max ----
        float wma = fmaxf(fmaxf(sacc[0][0], sacc[0][1]), fmaxf(sacc[1][0], sacc[1][1]));
        wma = fmaxf(wma, fmaxf(fmaxf(sacc[2][0], sacc[2][1]), fmaxf(sacc[3][0], sacc[3][1])));
        float wmb = fmaxf(fmaxf(sacc[0][2], sacc[0][3]), fmaxf(sacc[1][2], sacc[1][3]));
        wmb = fmaxf(wmb, fmaxf(fmaxf(sacc[2][2], sacc[2][3]), fmaxf(sacc[3][2], sacc[3][3])));
        wma = fmaxf(wma, __shfl_xor_sync(0xffffffffu, wma, 1));
        wma = fmaxf(wma, __shfl_xor_sync(0xffffffffu, wma, 2));
        wmb = fmaxf(wmb, __shfl_xor_sync(0xffffffffu, wmb, 1));
        wmb = fmaxf(wmb, __shfl_xor_sync(0xffffffffu, wmb, 2));
        if (tig == 0) { redm[ch * 64 + ra] = wma; redm[ch * 64 + rb] = wmb; }
        __syncthreads();
        float Ma = fmaxf(wma, redm[(ch ^ 1) * 64 + ra]);
        float Mb = fmaxf(wmb, redm[(ch ^ 1) * 64 + rb]);
        float nma = fmaxf(m_a, Ma), nmb = fmaxf(m_b, Mb);
        float ca = __expf(m_a - nma), cb = __expf(m_b - nmb);
        m_a = nma; m_b = nmb;

        float sa = 0.f, sb = 0.f;
#pragma unroll
        for (int j = 0; j < 4; j++) {
            sacc[j][0] = __expf(sacc[j][0] - nma);
            sacc[j][1] = __expf(sacc[j][1] - nma);
            sacc[j][2] = __expf(sacc[j][2] - nmb);
            sacc[j][3] = __expf(sacc[j][3] - nmb);
            sa += sacc[j][0] + sacc[j][1];
            sb += sacc[j][2] + sacc[j][3];
        }
        sa += __shfl_xor_sync(0xffffffffu, sa, 1);
        sa += __shfl_xor_sync(0xffffffffu, sa, 2);
        sb += __shfl_xor_sync(0xffffffffu, sb, 1);
        sb += __shfl_xor_sync(0xffffffffu, sb, 2);

        // stage P into Ks (K reads all complete before previous barrier)
#pragma unroll
        for (int j = 0; j < 4; j++) {
            *reinterpret_cast<float2*>(&Ks[ra * 68 + n0c + 8 * j + 2 * tig]) = make_float2(sacc[j][0], sacc[j][1]);
            *reinterpret_cast<float2*>(&Ks[rb * 68 + n0c + 8 * j + 2 * tig]) = make_float2(sacc[j][2], sacc[j][3]);
        }
        if (tig == 0) { reds[ch * 64 + ra] = sa; reds[ch * 64 + rb] = sb; }
        __syncthreads();
        l_a = l_a * ca + sa + reds[(ch ^ 1) * 64 + ra];
        l_b = l_b * cb + sb + reds[(ch ^ 1) * 64 + rb];
#pragma unroll
        for (int j = 0; j < 4; j++) {
            oacc[j][0] *= ca; oacc[j][1] *= ca;
            oacc[j][2] *= cb; oacc[j][3] *= cb;
        }

        // ---- O += P @ V (rows m0.., output cols n0c..) ----
#pragma unroll
        for (int kk = 0; kk < 64; kk += 8) {
            unsigned a[4];
            a[0] = f2tf(Ks[ra * 68 + kk + tig]);
            a[1] = f2tf(Ks[rb * 68 + kk + tig]);
            a[2] = f2tf(Ks[ra * 68 + kk + tig + 4]);
            a[3] = f2tf(Ks[rb * 68 + kk + tig + 4]);
#pragma unroll
            for (int j = 0; j < 4; j++) {
                unsigned b[2];
                b[0] = f2tf(Vs[(kk + tig) * 72 + n0c + 8 * j + gid]);
                b[1] = f2tf(Vs[(kk + tig + 4) * 72 + n0c + 8 * j + gid]);
                mma8(oacc[j], a, b);
            }
        }
        __syncthreads();   // before next t overwrites Ks/Vs
    }

    const float ia = 1.f / l_a, ib = 1.f / l_b;
    float* op = g_obuf + ((size_t)bh * L_ + n * 64) * D_;
#pragma unroll
    for (int j = 0; j < 4; j++) {
        *reinterpret_cast<float2*>(&op[ra * 64 + n0c + 8 * j + 2 * tig]) =
            make_float2(oacc[j][0] * ia, oacc[j][1] * ia);
        *reinterpret_cast<float2*>(&op[rb * 64 + n0c + 8 * j + 2 * tig]) =
            make_float2(oacc[j][2] * ib, oacc[j][3] * ib);
    }
}

// ---------------- K5a: feature map = softmax over D for q and k ----------------
__global__ void k_featmap() {
    const int which = blockIdx.y;
    const float* src = which ? g_k : g_q;
    float* dst = which ? g_ck : g_cq;
    const int warp = threadIdx.x >> 5, lane = threadIdx.x & 31;
    const size_t row = (size_t)blockIdx.x * 8 + warp;
    const float* p = src + row * 64;
    float v0 = p[lane], v1 = p[lane + 32];
    float m = fmaxf(v0, v1);
#pragma unroll
    for (int o = 16; o; o >>= 1) m = fmaxf(m, __shfl_xor_sync(0xffffffffu, m, o));
    v0 = __expf(v0 - m); v1 = __expf(v1 - m);
    float s = v0 + v1;
#pragma unroll
    for (int o = 16; o; o >>= 1) s += __shfl_xor_sync(0xffffffffu, s, o);
    float inv = 1.f / s;
    dst[row * 64 + lane] = v0 * inv;
    dst[row * 64 + lane + 32] = v1 * inv;
}

// ---------------- K5b: per key block: kvb = cK^T @ V (DxD), ksum = colsum(cK) ----------------
__global__ void k_kvb() {
    __shared__ float CK[64][68];
    __shared__ float Vs[64][68];
    const int m = blockIdx.x, bh = blockIdx.y;
    const int tid = threadIdx.x;
    const float* ckp = g_ck + ((size_t)bh * L_ + m * 64) * D_;
    const float* vp  = g_v  + ((size_t)bh * L_ + m * 64) * D_;
    for (int i = tid * 4; i < 4096; i += 1024) {
        int r = i >> 6, d = i & 63;
        *reinterpret_cast<float4*>(&CK[r][d]) = *reinterpret_cast<const float4*>(&ckp[i]);
        *reinterpret_cast<float4*>(&Vs[r][d]) = *reinterpret_cast<const float4*>(&vp[i]);
    }
    __syncthreads();
    const int ty = tid >> 4, tx = tid & 15, d0 = ty * 4, e0 = tx * 4;
    float acc[4][4] = {};
    for (int k = 0; k < 64; k++) {
        float4 a4 = *reinterpret_cast<float4*>(&CK[k][d0]);
        float a[4] = {a4.x, a4.y, a4.z, a4.w};
        float4 bv = *reinterpret_cast<float4*>(&Vs[k][e0]);
#pragma unroll
        for (int i = 0; i < 4; i++) {
            acc[i][0] += a[i] * bv.x; acc[i][1] += a[i] * bv.y;
            acc[i][2] += a[i] * bv.z; acc[i][3] += a[i] * bv.w;
        }
    }
    float* dst = g_kvb + (size_t)(bh * NB_ + m) * D_ * D_;
#pragma unroll
    for (int i = 0; i < 4; i++)
        *reinterpret_cast<float4*>(&dst[(d0 + i) * 64 + e0]) =
            make_float4(acc[i][0], acc[i][1], acc[i][2], acc[i][3]);
    if (tid < 64) {
        float s = 0.f;
#pragma unroll 8
        for (int k = 0; k < 64; k++) s += CK[k][tid];
        g_ksum[(size_t)(bh * NB_ + m) * D_ + tid] = s;
    }
}

// ---------------- K5c: totals over all key blocks ----------------
__global__ void k_totals() {
    const int bh = blockIdx.x, tid = threadIdx.x;
    for (int i = tid; i < 4096; i += 256) {
        const float* p = g_kvb + (size_t)bh * NB_ * 4096 + i;
        float s = 0.f;
#pragma unroll 8
        for (int m = 0; m < 64; m++) s += p[(size_t)m * 4096];
        g_kvt[(size_t)bh * 4096 + i] = s;
    }
    if (tid < 64) {
        const float* p = g_ksum + (size_t)bh * NB_ * 64 + tid;
        float s = 0.f;
#pragma unroll 8
        for (int m = 0; m < 64; m++) s += p[m * 64];
        g_kst[bh * 64 + tid] = s;
    }
}

// ---------------- K5d: linear path per query block + proj_l, add into obuf ----------------
__global__ void k_linfinal(const float* __restrict__ plw, const float* __restrict__ plb) {
    __shared__ float A[64][68];
    __shared__ float Bm[64][68];
    __shared__ float ksq[64], den_s[64];
    __shared__ int luts[T_];
    const int n = blockIdx.x, bh = blockIdx.y;
    const int tid = threadIdx.x;
    if (tid < T_) luts[tid] = g_lut[((size_t)bh * NB_ + n) * T_ + tid];
    __syncthreads();
    for (int i = tid; i < 4096; i += 256) {
        float s = g_kvt[(size_t)bh * 4096 + i];
#pragma unroll
        for (int t = 0; t < T_; t++) s -= g_kvb[(size_t)(bh * NB_ + luts[t]) * 4096 + i];
        A[i >> 6][i & 63] = s;
    }
    if (tid < 64) {
        float s = g_kst[bh * 64 + tid];
#pragma unroll
        for (int t = 0; t < T_; t++) s -= g_ksum[(size_t)(bh * NB_ + luts[t]) * 64 + tid];
        ksq[tid] = s;
    }
    const float* cqp = g_cq + ((size_t)bh * L_ + n * 64) * D_;
    for (int i = tid * 4; i < 4096; i += 1024) {
        int r = i >> 6, d = i & 63;
        *reinterpret_cast<float4*>(&Bm[r][d]) = *reinterpret_cast<const float4*>(&cqp[i]);
    }
    __syncthreads();
    const int ty = tid >> 4, tx = tid & 15, r0 = ty * 4, c0 = tx * 4;
    float acc[4][4] = {};
    for (int d = 0; d < 64; d++) {
        float a[4];
#pragma unroll
        for (int i = 0; i < 4; i++) a[i] = Bm[r0 + i][d];
        float4 bv = *reinterpret_cast<float4*>(&A[d][c0]);
#pragma unroll
        for (int i = 0; i < 4; i++) {
            acc[i][0] += a[i] * bv.x; acc[i][1] += a[i] * bv.y;
            acc[i][2] += a[i] * bv.z; acc[i][3] += a[i] * bv.w;
        }
    }
    if (tid < 64) {
        float s = 0.f;
#pragma unroll 8
        for (int d = 0; d < 64; d++) s += Bm[tid][d] * ksq[d];
        den_s[tid] = s;
    }
    __syncthreads();
#pragma unroll
    for (int i = 0; i < 4; i++) {
        float inv = 1.f / (den_s[r0 + i] + 1e-6f);
#pragma unroll
        for (int j = 0; j < 4; j++) A[r0 + i][c0 + j] = acc[i][j] * inv;
    }
    for (int i = tid * 4; i < 4096; i += 1024) {
        int e = i >> 6, d = i & 63;
        *reinterpret_cast<float4*>(&Bm[e][d]) = *reinterpret_cast<const float4*>(&plw[i]);
    }
    __syncthreads();
    float acc2[4][4] = {};
    for (int d = 0; d < 64; d++) {
        float a[4], bb[4];
#pragma unroll
        for (int i = 0; i < 4; i++) a[i] = A[r0 + i][d];
#pragma unroll
        for (int j = 0; j < 4; j++) bb[j] = Bm[c0 + j][d];
#pragma unroll
        for (int i = 0; i < 4; i++)
#pragma unroll
            for (int j = 0; j < 4; j++) acc2[i][j] += a[i] * bb[j];
    }
    float pb0 = plb[c0], pb1 = plb[c0 + 1], pb2 = plb[c0 + 2], pb3 = plb[c0 + 3];
    float* op = g_obuf + ((size_t)bh * L_ + n * 64) * D_;
#pragma unroll
    for (int i = 0; i < 4; i++) {
        float4 v = *reinterpret_cast<float4*>(&op[(r0 + i) * 64 + c0]);
        v.x += acc2[i][0] + pb0; v.y += acc2[i][1] + pb1;
        v.z += acc2[i][2] + pb2; v.w += acc2[i][3] + pb3;
        *reinterpret_cast<float4*>(&op[(r0 + i) * 64 + c0]) = v;
    }
}

// ---------------- K6: out_proj GEMM, (256x256) @ (256,4096) per batch ----------------
__global__ void k_outproj(const float* __restrict__ w2, float* __restrict__ out) {
    __shared__ float As[16][68];
    __shared__ float Ws[16][64];
    const int l0 = blockIdx.x * 64, co0 = blockIdx.y * 64, b = blockIdx.z;
    const int tid = threadIdx.x;
    const int ty = tid >> 4, tx = tid & 15;
    float acc[4][4] = {};
    for (int c0 = 0; c0 < C_; c0 += 16) {
        const int h = c0 >> 6, d0 = c0 & 63;
        const float* ap = g_obuf + ((size_t)(b * NH_ + h) * L_ + l0) * D_ + d0;
        {
            int i = tid * 4, l = i >> 4, d = i & 15;
            float4 v = *reinterpret_cast<const float4*>(&ap[(size_t)l * D_ + d]);
            As[d + 0][l] = v.x; As[d + 1][l] = v.y; As[d + 2][l] = v.z; As[d + 3][l] = v.w;
        }
        {
            int i = tid * 4, o = i >> 4, c = i & 15;
            float4 v = *reinterpret_cast<const float4*>(&w2[(size_t)(co0 + o) * C_ + c0 + c]);
            Ws[c + 0][o] = v.x; Ws[c + 1][o] = v.y; Ws[c + 2][o] = v.z; Ws[c + 3][o] = v.w;
        }
        __syncthreads();
#pragma unroll
        for (int c = 0; c < 16; c++) {
            float4 a4 = *reinterpret_cast<float4*>(&Ws[c][ty * 4]);
            float4 b4 = *reinterpret_cast<float4*>(&As[c][tx * 4]);
            float a[4] = {a4.x, a4.y, a4.z, a4.w};
            float bb[4] = {b4.x, b4.y, b4.z, b4.w};
#pragma unroll
            for (int i = 0; i < 4; i++)
#pragma unroll
                for (int j = 0; j < 4; j++) acc[i][j] += a[i] * bb[j];
        }
        __syncthreads();
    }
#pragma unroll
    for (int i = 0; i < 4; i++) {
        int co = co0 + ty * 4 + i;
        *reinterpret_cast<float4*>(&out[(size_t)b * C_ * L_ + (size_t)co * L_ + l0 + tx * 4]) =
            make_float4(acc[i][0], acc[i][1], acc[i][2], acc[i][3]);
    }
}

// ---------------- launch ----------------
extern "C" void kernel_launch(void* const* d_in, const int* in_sizes, int n_in,
                              void* d_out, int out_size) {
    const float* x     = (const float*)d_in[0];
    const float* qkv_w = (const float*)d_in[1];
    const float* out_w = (const float*)d_in[2];
    const float* plw   = (const float*)d_in[3];
    const float* plb   = (const float*)d_in[4];
    float* out = (float*)d_out;

    const int sattn_smem = SATTN_SMEM_FLOATS * (int)sizeof(float); // 54272 B
    cudaFuncSetAttribute(k_sattn, cudaFuncAttributeMaxDynamicSharedMemorySize, sattn_smem);

    k_qkv      <<<dim3(L_ / 64, 12, B_), 256>>>(x, qkv_w);
    k_blockmean<<<dim3(NB_, BH_, 2), 64>>>();
    k_topk     <<<BH_, 256>>>();
    k_sattn    <<<dim3(NB_, BH_), 256, sattn_smem>>>();
    k_featmap  <<<dim3(BH_ * L_ / 8, 2), 256>>>();
    k_kvb      <<<dim3(NB_, BH_), 256>>>();
    k_totals   <<<BH_, 256>>>();
    k_linfinal <<<dim3(NB_, BH_), 256>>>(plw, plb);
    k_outproj  <<<dim3(L_ / 64, C_ / 64, B_), 256>>>(out_w, out);
}